// round 3
// baseline (speedup 1.0000x reference)
#include <cuda_runtime.h>
#include <cstdint>

#define NMAX 50048
#define EMAX 1000000
#define FD 128     // H*F_OUT == F_IN == 128
#define HH 8       // heads
#define SB 1024

// Scratch (static __device__ — no allocations allowed)
__device__ float g_xp[(size_t)NMAX * FD];      // x @ W            [N,128]
__device__ float g_asrc[(size_t)NMAX * HH];    // a_src            [N,8]
__device__ float g_adst[(size_t)NMAX * HH];    // a_dst            [N,8]
__device__ int   g_cnt[NMAX + 1];              // per-dst degree
__device__ int   g_rowstart[NMAX + 1];         // CSR row offsets
__device__ int   g_cursor[NMAX];               // scatter cursors
__device__ int   g_csr[EMAX];                  // src indices, grouped by dst

__device__ __forceinline__ void ffma2(unsigned long long& d,
                                      unsigned long long a,
                                      unsigned long long b) {
    asm("fma.rn.f32x2 %0, %1, %2, %0;" : "+l"(d) : "l"(a), "l"(b));
}
__device__ __forceinline__ unsigned long long pack2(float lo, float hi) {
    unsigned long long r;
    asm("mov.b64 %0, {%1,%2};" : "=l"(r) : "f"(lo), "f"(hi));
    return r;
}
__device__ __forceinline__ float unpack_sum(unsigned long long v) {
    float lo, hi;
    asm("mov.b64 {%0,%1}, %2;" : "=f"(lo), "=f"(hi) : "l"(v));
    return lo + hi;
}

// ---------------------------------------------------------------------------
// xp = x @ W via packed f32x2 FMA (+ fused attention logits a_src, a_dst).
// acc2[r].lo accumulates even-k partials, .hi odd-k; summed at the end.
// ---------------------------------------------------------------------------
__global__ void gemm_kernel(const float* __restrict__ x,
                            const float* __restrict__ W,
                            const float* __restrict__ att_src,
                            const float* __restrict__ att_dst,
                            int n) {
    __shared__ float4 xs4[32 * 32];           // 32 rows x 32 float4 (k-major rows)
    const int c  = threadIdx.x;               // output column 0..127
    const int r0 = blockIdx.x * 32;
    const int rows = min(32, n - r0);

    const float4* x4 = (const float4*)x;
    for (int i = threadIdx.x; i < rows * 32; i += 128) {
        int r = i >> 5, k4 = i & 31;
        xs4[r * 32 + k4] = x4[(size_t)(r0 + r) * 32 + k4];
    }
    __syncthreads();

    unsigned long long acc2[32];
#pragma unroll
    for (int r = 0; r < 32; r++) acc2[r] = 0ull;

    const ulonglong2* xs2 = (const ulonglong2*)xs4;
#pragma unroll 4
    for (int k4 = 0; k4 < 32; k4++) {
        float w0 = W[(k4 * 4 + 0) * FD + c];
        float w1 = W[(k4 * 4 + 1) * FD + c];
        float w2 = W[(k4 * 4 + 2) * FD + c];
        float w3 = W[(k4 * 4 + 3) * FD + c];
        unsigned long long w2a = pack2(w0, w1);
        unsigned long long w2b = pack2(w2, w3);
#pragma unroll
        for (int r = 0; r < 32; r++) {
            ulonglong2 xv = xs2[r * 32 + k4];  // LDS.128 broadcast: (k,k+1),(k+2,k+3)
            ffma2(acc2[r], xv.x, w2a);
            ffma2(acc2[r], xv.y, w2b);
        }
    }

    const float a_s = att_src[c];
    const float a_d = att_dst[c];
    const int lane = threadIdx.x & 31;
    for (int r = 0; r < rows; r++) {
        float v = unpack_sum(acc2[r]);
        g_xp[(size_t)(r0 + r) * FD + c] = v;
        float vs = v * a_s, vd = v * a_d;
#pragma unroll
        for (int off = 8; off; off >>= 1) {
            vs += __shfl_xor_sync(0xffffffffu, vs, off, 16);
            vd += __shfl_xor_sync(0xffffffffu, vd, off, 16);
        }
        if ((lane & 15) == 0) {
            int h = c >> 4;
            g_asrc[(size_t)(r0 + r) * HH + h] = vs;
            g_adst[(size_t)(r0 + r) * HH + h] = vd;
        }
    }
}

// ---------------------------------------------------------------------------
// CSR build
// ---------------------------------------------------------------------------
__global__ void zerocnt_kernel(int n) {
    int i = blockIdx.x * blockDim.x + threadIdx.x;
    if (i <= n) g_cnt[i] = 0;
}

__global__ void hist_kernel(const int* __restrict__ ei, int E) {
    int e = blockIdx.x * blockDim.x + threadIdx.x;
    if (e < E) atomicAdd(&g_cnt[ei[E + e]], 1);
}

// Single-block exclusive scan of g_cnt[0..n-1] -> g_rowstart[0..n], g_cursor.
__global__ void scan_kernel(int n) {
    const int t = threadIdx.x;
    const int per = (n + SB - 1) / SB;
    const int beg = t * per;
    const int fin = min(beg + per, n);

    int sum = 0;
    for (int i = beg; i < fin; i++) sum += g_cnt[i];

    // block exclusive scan of per-thread sums
    const int lane = t & 31, wid = t >> 5;
    int xv = sum;
#pragma unroll
    for (int off = 1; off < 32; off <<= 1) {
        int y = __shfl_up_sync(0xffffffffu, xv, off);
        if (lane >= off) xv += y;
    }
    __shared__ int ws[32];
    if (lane == 31) ws[wid] = xv;
    __syncthreads();
    if (wid == 0) {
        int s = ws[lane];
#pragma unroll
        for (int off = 1; off < 32; off <<= 1) {
            int y = __shfl_up_sync(0xffffffffu, s, off);
            if (lane >= off) s += y;
        }
        ws[lane] = s;
    }
    __syncthreads();
    int run = xv - sum + (wid ? ws[wid - 1] : 0);

    for (int i = beg; i < fin; i++) {
        g_rowstart[i] = run;
        g_cursor[i]   = run;
        run += g_cnt[i];
    }
    if (t == SB - 1 || fin == n) {
        if (beg <= n && run >= 0 && t == SB - 1) g_rowstart[n] = ws[31];
    }
    if (t == 0) g_rowstart[n] = ws[31];   // total
}

__global__ void scatter_kernel(const int* __restrict__ ei, int E) {
    int e = blockIdx.x * blockDim.x + threadIdx.x;
    if (e < E) {
        int d = ei[E + e];
        int p = atomicAdd(&g_cursor[d], 1);
        g_csr[p] = ei[e];
    }
}

// ---------------------------------------------------------------------------
// Fused aggregate + softmax-normalize + bias + LayerNorm.
// One warp per destination node; lane l owns features [4l,4l+4).
// 2-way edge unroll for MLP. No segment-max needed (self-loops guarantee
// z>0; unshifted exp exact to fp32 tolerance at these logit scales).
// ---------------------------------------------------------------------------
__global__ void agg_kernel(const float* __restrict__ bias,
                           const float* __restrict__ gamma,
                           const float* __restrict__ beta,
                           float* __restrict__ out, int n) {
    const int wrp = (blockIdx.x * blockDim.x + threadIdx.x) >> 5;
    if (wrp >= n) return;
    const int lane = threadIdx.x & 31;
    const int h = lane >> 2;

    const int row = g_rowstart[wrp];
    const int end = g_rowstart[wrp + 1];
    const float adh = g_adst[(size_t)wrp * HH + h];
    const float4* __restrict__ xp4 = (const float4*)g_xp;

    float4 acc = make_float4(0.f, 0.f, 0.f, 0.f);
    float wsum = 0.f;

    int i = row;
    for (; i + 1 < end; i += 2) {
        int s0 = g_csr[i];
        int s1 = g_csr[i + 1];
        float a0 = g_asrc[(size_t)s0 * HH + h];
        float a1 = g_asrc[(size_t)s1 * HH + h];
        float4 x0 = xp4[(size_t)s0 * 32 + lane];
        float4 x1 = xp4[(size_t)s1 * 32 + lane];
        float v0 = a0 + adh; v0 = v0 > 0.f ? v0 : 0.2f * v0;
        float v1 = a1 + adh; v1 = v1 > 0.f ? v1 : 0.2f * v1;
        float w0 = __expf(v0);
        float w1 = __expf(v1);
        acc.x = fmaf(w0, x0.x, acc.x); acc.y = fmaf(w0, x0.y, acc.y);
        acc.z = fmaf(w0, x0.z, acc.z); acc.w = fmaf(w0, x0.w, acc.w);
        acc.x = fmaf(w1, x1.x, acc.x); acc.y = fmaf(w1, x1.y, acc.y);
        acc.z = fmaf(w1, x1.z, acc.z); acc.w = fmaf(w1, x1.w, acc.w);
        wsum += w0 + w1;
    }
    if (i < end) {
        int s = g_csr[i];
        float v = g_asrc[(size_t)s * HH + h] + adh;
        v = v > 0.f ? v : 0.2f * v;
        float wgt = __expf(v);
        float4 xv = xp4[(size_t)s * 32 + lane];
        acc.x = fmaf(wgt, xv.x, acc.x); acc.y = fmaf(wgt, xv.y, acc.y);
        acc.z = fmaf(wgt, xv.z, acc.z); acc.w = fmaf(wgt, xv.w, acc.w);
        wsum += wgt;
    }

    // self loop
    {
        float v = g_asrc[(size_t)wrp * HH + h] + adh;
        v = v > 0.f ? v : 0.2f * v;
        float wgt = __expf(v);
        float4 xv = xp4[(size_t)wrp * 32 + lane];
        acc.x = fmaf(wgt, xv.x, acc.x); acc.y = fmaf(wgt, xv.y, acc.y);
        acc.z = fmaf(wgt, xv.z, acc.z); acc.w = fmaf(wgt, xv.w, acc.w);
        wsum += wgt;
    }

    const float inv_w = 1.f / wsum;
    float4 b4 = ((const float4*)bias)[lane];
    float4 o;
    o.x = acc.x * inv_w + b4.x;
    o.y = acc.y * inv_w + b4.y;
    o.z = acc.z * inv_w + b4.z;
    o.w = acc.w * inv_w + b4.w;

    float s1 = o.x + o.y + o.z + o.w;
    float s2 = o.x * o.x + o.y * o.y + o.z * o.z + o.w * o.w;
#pragma unroll
    for (int off = 16; off; off >>= 1) {
        s1 += __shfl_xor_sync(0xffffffffu, s1, off);
        s2 += __shfl_xor_sync(0xffffffffu, s2, off);
    }
    float mu  = s1 * (1.f / 128.f);
    float var = s2 * (1.f / 128.f) - mu * mu;
    float inv = rsqrtf(var + 1e-5f);

    float4 g4 = ((const float4*)gamma)[lane];
    float4 e4 = ((const float4*)beta)[lane];
    float4 r;
    r.x = (o.x - mu) * inv * g4.x + e4.x;
    r.y = (o.y - mu) * inv * g4.y + e4.y;
    r.z = (o.z - mu) * inv * g4.z + e4.z;
    r.w = (o.w - mu) * inv * g4.w + e4.w;
    ((float4*)out)[(size_t)wrp * 32 + lane] = r;
}

// ---------------------------------------------------------------------------
extern "C" void kernel_launch(void* const* d_in, const int* in_sizes, int n_in,
                              void* d_out, int out_size) {
    const float* x       = (const float*)d_in[0];
    const int*   ei      = (const int*)d_in[1];
    const float* W       = (const float*)d_in[2];
    const float* att_src = (const float*)d_in[3];
    const float* att_dst = (const float*)d_in[4];
    const float* bias    = (const float*)d_in[5];
    const float* gamma   = (const float*)d_in[6];
    const float* beta    = (const float*)d_in[7];
    float* out = (float*)d_out;

    const int n = in_sizes[0] / FD;   // 50000
    const int E = in_sizes[1] / 2;    // 800000

    zerocnt_kernel<<<(n + 1 + 255) / 256, 256>>>(n);
    hist_kernel<<<(E + 255) / 256, 256>>>(ei, E);
    scan_kernel<<<1, SB>>>(n);
    scatter_kernel<<<(E + 255) / 256, 256>>>(ei, E);

    gemm_kernel<<<(n + 31) / 32, 128>>>(x, W, att_src, att_dst, n);
    agg_kernel<<<(n * 32 + 255) / 256, 256>>>(bias, gamma, beta, out, n);
}

// round 4
// speedup vs baseline: 1.3297x; 1.3297x over previous
#include <cuda_runtime.h>
#include <cstdint>

#define NMAX 50048
#define EMAX 1000000
#define FD 128     // H*F_OUT == F_IN == 128
#define HH 8       // heads
#define SB 1024    // scan block size

// Scratch (static __device__ — no allocations allowed)
__device__ float g_xp[(size_t)NMAX * FD];      // x @ W            [N,128]
__device__ float g_asrc[(size_t)NMAX * HH];    // a_src            [N,8]
__device__ float g_adst[(size_t)NMAX * HH];    // a_dst            [N,8]
__device__ int   g_cnt[NMAX + 1];              // per-dst degree
__device__ int   g_rowstart[NMAX + 1];         // CSR row offsets
__device__ int   g_cursor[NMAX];               // scatter cursors
__device__ int   g_bsum[64];                   // scan block sums
__device__ int   g_csr[EMAX];                  // src indices, grouped by dst

// ---------------------------------------------------------------------------
// xp = x @ W  (+ fused per-node attention logits a_src, a_dst)
// Scalar FFMA version (R2 — the FFMA2 variant regressed due to reg pairing).
// ---------------------------------------------------------------------------
__global__ void gemm_kernel(const float* __restrict__ x,
                            const float* __restrict__ W,
                            const float* __restrict__ att_src,
                            const float* __restrict__ att_dst,
                            int n) {
    __shared__ float4 xs4[32 * 32];           // 32 rows x 32 float4
    const int c  = threadIdx.x;               // output column 0..127
    const int r0 = blockIdx.x * 32;
    const int rows = min(32, n - r0);

    const float4* x4 = (const float4*)x;
    for (int i = threadIdx.x; i < rows * 32; i += 128) {
        int r = i >> 5, k4 = i & 31;
        xs4[r * 32 + k4] = x4[(size_t)(r0 + r) * 32 + k4];
    }
    __syncthreads();

    float acc[32];
#pragma unroll
    for (int r = 0; r < 32; r++) acc[r] = 0.f;

#pragma unroll 4
    for (int k4 = 0; k4 < 32; k4++) {
        float w0 = W[(k4 * 4 + 0) * FD + c];
        float w1 = W[(k4 * 4 + 1) * FD + c];
        float w2 = W[(k4 * 4 + 2) * FD + c];
        float w3 = W[(k4 * 4 + 3) * FD + c];
#pragma unroll
        for (int r = 0; r < 32; r++) {
            float4 xv = xs4[r * 32 + k4];     // broadcast LDS.128
            acc[r] = fmaf(xv.x, w0, acc[r]);
            acc[r] = fmaf(xv.y, w1, acc[r]);
            acc[r] = fmaf(xv.z, w2, acc[r]);
            acc[r] = fmaf(xv.w, w3, acc[r]);
        }
    }

    const float a_s = att_src[c];
    const float a_d = att_dst[c];
    const int lane = threadIdx.x & 31;
    for (int r = 0; r < rows; r++) {
        float v = acc[r];
        g_xp[(size_t)(r0 + r) * FD + c] = v;
        float vs = v * a_s, vd = v * a_d;
#pragma unroll
        for (int off = 8; off; off >>= 1) {
            vs += __shfl_xor_sync(0xffffffffu, vs, off, 16);
            vd += __shfl_xor_sync(0xffffffffu, vd, off, 16);
        }
        if ((lane & 15) == 0) {
            int h = c >> 4;
            g_asrc[(size_t)(r0 + r) * HH + h] = vs;
            g_adst[(size_t)(r0 + r) * HH + h] = vd;
        }
    }
}

// ---------------------------------------------------------------------------
// CSR build: zero -> histogram -> scan (3 kernels, parallel middle) -> scatter
// ---------------------------------------------------------------------------
__global__ void zerocnt_kernel(int n) {
    int i = blockIdx.x * blockDim.x + threadIdx.x;
    if (i <= n) g_cnt[i] = 0;
}

__global__ void hist_kernel(const int* __restrict__ ei, int E) {
    int e = blockIdx.x * blockDim.x + threadIdx.x;
    if (e < E) atomicAdd(&g_cnt[ei[E + e]], 1);
}

__global__ void scan1_kernel(int n) {
    const int i = blockIdx.x * SB + threadIdx.x;
    const int lane = threadIdx.x & 31, wid = threadIdx.x >> 5;
    int v = (i < n) ? g_cnt[i] : 0;
    int x = v;
#pragma unroll
    for (int off = 1; off < 32; off <<= 1) {
        int y = __shfl_up_sync(0xffffffffu, x, off);
        if (lane >= off) x += y;
    }
    __shared__ int ws[32];
    if (lane == 31) ws[wid] = x;
    __syncthreads();
    if (wid == 0) {
        int s = ws[lane];
#pragma unroll
        for (int off = 1; off < 32; off <<= 1) {
            int y = __shfl_up_sync(0xffffffffu, s, off);
            if (lane >= off) s += y;
        }
        ws[lane] = s;
    }
    __syncthreads();
    int excl = x - v + (wid ? ws[wid - 1] : 0);
    if (i <= n) g_rowstart[i] = excl;
    if (threadIdx.x == SB - 1) g_bsum[blockIdx.x] = excl + v;
}

// Parallel warp-shuffle exclusive scan over up to 64 block sums (1 warp).
__global__ void scan2_kernel(int nb) {
    const int lane = threadIdx.x;             // 32 threads
    int v0 = (lane < nb) ? g_bsum[lane] : 0;
    int v1 = (lane + 32 < nb) ? g_bsum[lane + 32] : 0;

    int x0 = v0;
#pragma unroll
    for (int off = 1; off < 32; off <<= 1) {
        int y = __shfl_up_sync(0xffffffffu, x0, off);
        if (lane >= off) x0 += y;
    }
    int tot0 = __shfl_sync(0xffffffffu, x0, 31);
    int x1 = v1;
#pragma unroll
    for (int off = 1; off < 32; off <<= 1) {
        int y = __shfl_up_sync(0xffffffffu, x1, off);
        if (lane >= off) x1 += y;
    }
    if (lane < nb)      g_bsum[lane]      = x0 - v0;
    if (lane + 32 < nb) g_bsum[lane + 32] = tot0 + x1 - v1;
}

__global__ void scan3_kernel(int n) {
    int i = blockIdx.x * SB + threadIdx.x;
    if (i <= n) {
        int v = g_rowstart[i] + g_bsum[blockIdx.x];
        g_rowstart[i] = v;
        if (i < n) g_cursor[i] = v;
    }
}

__global__ void scatter_kernel(const int* __restrict__ ei, int E) {
    int e = blockIdx.x * blockDim.x + threadIdx.x;
    if (e < E) {
        int d = ei[E + e];
        int p = atomicAdd(&g_cursor[d], 1);
        g_csr[p] = ei[e];
    }
}

// ---------------------------------------------------------------------------
// Fused aggregate + softmax-normalize + bias + LayerNorm.
// One warp per destination node; lane l owns features [4l,4l+4).
// 2-way edge unroll for MLP. No segment-max needed (self-loops guarantee
// z>0; unshifted exp exact to fp32 tolerance at these logit scales).
// ---------------------------------------------------------------------------
__global__ void agg_kernel(const float* __restrict__ bias,
                           const float* __restrict__ gamma,
                           const float* __restrict__ beta,
                           float* __restrict__ out, int n) {
    const int wrp = (blockIdx.x * blockDim.x + threadIdx.x) >> 5;
    if (wrp >= n) return;
    const int lane = threadIdx.x & 31;
    const int h = lane >> 2;

    const int row = g_rowstart[wrp];
    const int end = g_rowstart[wrp + 1];
    const float adh = g_adst[(size_t)wrp * HH + h];
    const float4* __restrict__ xp4 = (const float4*)g_xp;

    float4 acc = make_float4(0.f, 0.f, 0.f, 0.f);
    float wsum = 0.f;

    int i = row;
    for (; i + 1 < end; i += 2) {
        int s0 = g_csr[i];
        int s1 = g_csr[i + 1];
        float a0 = g_asrc[(size_t)s0 * HH + h];
        float a1 = g_asrc[(size_t)s1 * HH + h];
        float4 x0 = xp4[(size_t)s0 * 32 + lane];
        float4 x1 = xp4[(size_t)s1 * 32 + lane];
        float v0 = a0 + adh; v0 = v0 > 0.f ? v0 : 0.2f * v0;
        float v1 = a1 + adh; v1 = v1 > 0.f ? v1 : 0.2f * v1;
        float w0 = __expf(v0);
        float w1 = __expf(v1);
        acc.x = fmaf(w0, x0.x, acc.x); acc.y = fmaf(w0, x0.y, acc.y);
        acc.z = fmaf(w0, x0.z, acc.z); acc.w = fmaf(w0, x0.w, acc.w);
        acc.x = fmaf(w1, x1.x, acc.x); acc.y = fmaf(w1, x1.y, acc.y);
        acc.z = fmaf(w1, x1.z, acc.z); acc.w = fmaf(w1, x1.w, acc.w);
        wsum += w0 + w1;
    }
    if (i < end) {
        int s = g_csr[i];
        float v = g_asrc[(size_t)s * HH + h] + adh;
        v = v > 0.f ? v : 0.2f * v;
        float wgt = __expf(v);
        float4 xv = xp4[(size_t)s * 32 + lane];
        acc.x = fmaf(wgt, xv.x, acc.x); acc.y = fmaf(wgt, xv.y, acc.y);
        acc.z = fmaf(wgt, xv.z, acc.z); acc.w = fmaf(wgt, xv.w, acc.w);
        wsum += wgt;
    }

    // self loop
    {
        float v = g_asrc[(size_t)wrp * HH + h] + adh;
        v = v > 0.f ? v : 0.2f * v;
        float wgt = __expf(v);
        float4 xv = xp4[(size_t)wrp * 32 + lane];
        acc.x = fmaf(wgt, xv.x, acc.x); acc.y = fmaf(wgt, xv.y, acc.y);
        acc.z = fmaf(wgt, xv.z, acc.z); acc.w = fmaf(wgt, xv.w, acc.w);
        wsum += wgt;
    }

    const float inv_w = 1.f / wsum;
    float4 b4 = ((const float4*)bias)[lane];
    float4 o;
    o.x = acc.x * inv_w + b4.x;
    o.y = acc.y * inv_w + b4.y;
    o.z = acc.z * inv_w + b4.z;
    o.w = acc.w * inv_w + b4.w;

    float s1 = o.x + o.y + o.z + o.w;
    float s2 = o.x * o.x + o.y * o.y + o.z * o.z + o.w * o.w;
#pragma unroll
    for (int off = 16; off; off >>= 1) {
        s1 += __shfl_xor_sync(0xffffffffu, s1, off);
        s2 += __shfl_xor_sync(0xffffffffu, s2, off);
    }
    float mu  = s1 * (1.f / 128.f);
    float var = s2 * (1.f / 128.f) - mu * mu;
    float inv = rsqrtf(var + 1e-5f);

    float4 g4 = ((const float4*)gamma)[lane];
    float4 e4 = ((const float4*)beta)[lane];
    float4 r;
    r.x = (o.x - mu) * inv * g4.x + e4.x;
    r.y = (o.y - mu) * inv * g4.y + e4.y;
    r.z = (o.z - mu) * inv * g4.z + e4.z;
    r.w = (o.w - mu) * inv * g4.w + e4.w;
    ((float4*)out)[(size_t)wrp * 32 + lane] = r;
}

// ---------------------------------------------------------------------------
extern "C" void kernel_launch(void* const* d_in, const int* in_sizes, int n_in,
                              void* d_out, int out_size) {
    const float* x       = (const float*)d_in[0];
    const int*   ei      = (const int*)d_in[1];
    const float* W       = (const float*)d_in[2];
    const float* att_src = (const float*)d_in[3];
    const float* att_dst = (const float*)d_in[4];
    const float* bias    = (const float*)d_in[5];
    const float* gamma   = (const float*)d_in[6];
    const float* beta    = (const float*)d_in[7];
    float* out = (float*)d_out;

    const int n = in_sizes[0] / FD;   // 50000
    const int E = in_sizes[1] / 2;    // 800000
    const int nb = (n + 1 + SB - 1) / SB;

    zerocnt_kernel<<<(n + 1 + 255) / 256, 256>>>(n);
    hist_kernel<<<(E + 255) / 256, 256>>>(ei, E);
    scan1_kernel<<<nb, SB>>>(n);
    scan2_kernel<<<1, 32>>>(nb);
    scan3_kernel<<<nb, SB>>>(n);
    scatter_kernel<<<(E + 255) / 256, 256>>>(ei, E);

    gemm_kernel<<<(n + 31) / 32, 128>>>(x, W, att_src, att_dst, n);
    agg_kernel<<<(n * 32 + 255) / 256, 256>>>(bias, gamma, beta, out, n);
}